// round 8
// baseline (speedup 1.0000x reference)
#include <cuda_runtime.h>
#include <cuda_bf16.h>

// Problem constants
#define NN        64
#define MM        2080          // N*(N+1)/2
#define NWORDS    65            // 2080/32
#define TOPK      5
#define NEIGHBOR  16
#define NEGATIVE  16
#define TOTAL     85
#define KOUT      101
#define BB        32
#define DD        512
#define NCHUNK    8             // 8 warp-sorted chunks of 256
#define CHUNK     256
#define SORTM     2048
#define NEXTRA    32            // MM - SORTM
#define THRS      256           // 8 warps

#define BK        (BB*KOUT)     // 3232
#define F1        (BK*DD)
#define F2        (F1 + BK*2)
#define F3        (F2 + BK*2)

__device__ int g_cell[BK];      // (b*NN+r)*NN+c per output row

__device__ __forceinline__ int tri_base(int r) { return r * (129 - r) / 2; }

__device__ __forceinline__ void cswap(unsigned long long& a, unsigned long long& b, bool up)
{
    if ((a > b) == up) { unsigned long long t = a; a = b; b = t; }
}

// In-register bitonic stage, J in {1,2,4}, over 8 contiguous elements el0..el0+7
template<int J, int K>
__device__ __forceinline__ void sreg(unsigned long long v[8], int el0)
{
    #pragma unroll
    for (int r = 0; r < 8; r++)
        if ((r & J) == 0) cswap(v[r], v[r + J], ((el0 + r) & K) == 0);
}

// Shuffle bitonic stage, J in {8..128}: partner lane = lane ^ (J/8)
template<int J, int K>
__device__ __forceinline__ void sshf(unsigned long long v[8], int el0)
{
    #pragma unroll
    for (int r = 0; r < 8; r++) {
        unsigned long long o = __shfl_xor_sync(0xFFFFFFFFu, v[r], J >> 3);
        int e = el0 + r;
        bool tm = (((e & J) == 0) == ((e & K) == 0));
        v[r] = ((v[r] < o) == tm) ? v[r] : o;
    }
}

// count of elements < key in ascending a[0..256) (keys unique). 9 probes.
__device__ __forceinline__ int lb256(const unsigned long long* __restrict__ a,
                                     unsigned long long key)
{
    int lo = 0;
    #pragma unroll
    for (int s = 128; s >= 1; s >>= 1)
        if (a[lo + s - 1] < key) lo += s;
    return lo + ((a[lo] < key) ? 1 : 0);
}

// count of elements < key in ascending a[0..32). 6 probes.
__device__ __forceinline__ int lb32(const unsigned long long* __restrict__ a,
                                    unsigned long long key)
{
    int lo = 0;
    #pragma unroll
    for (int s = 16; s >= 1; s >>= 1)
        if (a[lo + s - 1] < key) lo += s;
    return lo + ((a[lo] < key) ? 1 : 0);
}

__device__ __forceinline__ unsigned long long packkey(
    const float* sp, const unsigned char* rt, const unsigned char* ct, int m)
{
    unsigned u  = __float_as_uint(sp[(int)rt[m] * NN + (int)ct[m]]);
    unsigned sa = (u & 0x80000000u) ? ~u : (u | 0x80000000u);
    return ((unsigned long long)(~sa) << 32) | (unsigned)m;   // descending score, stable
}

// nbm = lowest `NEIGHBOR-cb` set bits (earliest sorted positions); OR into state
__device__ __forceinline__ void apply_word(unsigned* sup, unsigned* selb, int w, unsigned mk, int cb)
{
    sup[w] |= mk;
    unsigned nbm = 0u;
    if (cb < NEIGHBOR) {
        int keep = NEIGHBOR - cb;
        nbm = mk;
        int pc = __popc(mk);
        while (pc > keep) { nbm ^= (0x80000000u >> __clz(nbm)); pc--; }
    }
    selb[w] |= nbm;
}

__global__ __launch_bounds__(THRS)
void select_kernel(const float* __restrict__ score_pred,
                   const float* __restrict__ offset_gt,
                   const float* __restrict__ tmap,
                   float* __restrict__ out)
{
    __shared__ unsigned long long keys[SORTM];     // 8 ascending chunks of 256
    __shared__ unsigned long long fkeys[MM];       // merged final order
    __shared__ unsigned long long extras[NEXTRA];  // ascending
    __shared__ unsigned char rtab[MM], ctab[MM];
    __shared__ unsigned short se[MM];              // packed (s | e<<8) per sorted pos
    __shared__ unsigned int sup[NWORDS], selb[NWORDS], tmpm[NWORDS];
    __shared__ int Pun[NWORDS], Psel[NWORDS];
    __shared__ int midpos[TOTAL], negpos[NEGATIVE];
    __shared__ int s_nunsup, s_pad, s_first;

    const int b    = blockIdx.x;
    const int tid  = threadIdx.x;
    const int lane = tid & 31;
    const int wv   = tid >> 5;        // warp = chunk id (0..7)
    const int e0   = tid * 8;         // global idx of first owned element
    const int el0  = lane * 8;        // chunk-local idx (forces all-ascending)

    if (tid < NN) {
        int r = tid, base = tri_base(r);
        for (int c = r; c < NN; c++) {
            rtab[base + c - r] = (unsigned char)r;
            ctab[base + c - r] = (unsigned char)c;
        }
    }
    if (tid < NWORDS) { sup[tid] = 0u; selb[tid] = 0u; }
    if (tid < TOTAL)    midpos[tid] = MM - 1;
    if (tid < NEGATIVE) negpos[tid] = MM - 1;
    if (tid == 0) s_first = MM - 1;
    __syncthreads();

    const float* sp = score_pred + (size_t)b * NN * NN;
    unsigned long long v[8];
    #pragma unroll
    for (int r = 0; r < 8; r++) v[r] = packkey(sp, rtab, ctab, e0 + r);

    // ---- Warp-local ascending sort of this warp's 256-chunk (NO barriers) ----
    sreg<1,2>(v,el0);
    sreg<2,4>(v,el0);  sreg<1,4>(v,el0);
    sreg<4,8>(v,el0);  sreg<2,8>(v,el0);  sreg<1,8>(v,el0);
    sshf<8,16>(v,el0); sreg<4,16>(v,el0); sreg<2,16>(v,el0); sreg<1,16>(v,el0);
    sshf<16,32>(v,el0); sshf<8,32>(v,el0);
    sreg<4,32>(v,el0);  sreg<2,32>(v,el0); sreg<1,32>(v,el0);
    sshf<32,64>(v,el0); sshf<16,64>(v,el0); sshf<8,64>(v,el0);
    sreg<4,64>(v,el0);  sreg<2,64>(v,el0);  sreg<1,64>(v,el0);
    sshf<64,128>(v,el0); sshf<32,128>(v,el0); sshf<16,128>(v,el0); sshf<8,128>(v,el0);
    sreg<4,128>(v,el0);  sreg<2,128>(v,el0);  sreg<1,128>(v,el0);
    sshf<128,256>(v,el0); sshf<64,256>(v,el0); sshf<32,256>(v,el0);
    sshf<16,256>(v,el0);  sshf<8,256>(v,el0);
    sreg<4,256>(v,el0);   sreg<2,256>(v,el0); sreg<1,256>(v,el0);

    #pragma unroll
    for (int r = 0; r < 8; r++) keys[e0 + r] = v[r];

    // ---- Warp 0 sorts the 32 extras (ascending, shuffle bitonic) ----
    unsigned long long ek = 0;
    if (wv == 0) {
        ek = packkey(sp, rtab, ctab, SORTM + lane);
        #pragma unroll
        for (int kk = 2; kk <= 32; kk <<= 1)
            #pragma unroll
            for (int j = kk >> 1; j >= 1; j >>= 1) {
                unsigned long long o = __shfl_xor_sync(0xFFFFFFFFu, ek, j);
                bool tm = (((lane & j) == 0) == ((lane & kk) == 0));
                ek = ((ek < o) == tm) ? ek : o;
            }
        extras[lane] = ek;
    }
    __syncthreads();

    // ---- 9-way rank-merge scatter (keys unique -> rank is a permutation) ----
    #pragma unroll
    for (int r = 0; r < 8; r++) {
        unsigned long long x = v[r];
        int rank = el0 + r + lb32(extras, x);          // own-chunk count + extras
        #pragma unroll
        for (int c = 0; c < NCHUNK; c++)
            if (c != wv) rank += lb256(keys + c * CHUNK, x);
        int m = (int)(x & 0xFFFFFFFFu);
        fkeys[rank] = x;
        se[rank] = (unsigned short)((int)rtab[m] | (((int)ctab[m] + 1) << 8));
    }
    if (wv == 0) {
        int rank = lane;                               // own count among extras
        #pragma unroll
        for (int c = 0; c < NCHUNK; c++)
            rank += lb256(keys + c * CHUNK, ek);
        int m = (int)(ek & 0xFFFFFFFFu);
        fkeys[rank] = ek;
        se[rank] = (unsigned short)((int)rtab[m] | (((int)ctab[m] + 1) << 8));
    }
    __syncthreads();

    // ---- Cache this thread's 9 se values in registers ----
    unsigned short se9[9];
    #pragma unroll
    for (int c = 0; c < 9; c++) {
        int pos = c * THRS + tid;
        se9[c] = (pos < MM) ? se[pos] : (unsigned short)0;
    }

    // ---- Greedy selection: <= TOPK heavy iterations ----
    {
        int i = 0, cnt = 0;
        while (cnt < TOPK && i < MM - 1) {
            if ((sup[i >> 5] >> (i & 31)) & 1u) { i++; continue; }
            int se0 = se[i];
            int s0 = se0 & 0xFF, eH = se0 >> 8;

            #pragma unroll
            for (int c = 0; c < 9; c++) {
                int pos = c * THRS + tid;
                bool mbit = false;
                if (pos < MM && pos > i) {
                    int se1 = se9[c];
                    int s1 = se1 & 0xFF, e1 = se1 >> 8;
                    int inter = min(e1, eH) - max(s1, s0);
                    int uni   = max(e1, eH) - min(s1, s0);
                    mbit = (inter > 0) && (2 * inter > uni);   // iou > 0.5 exact
                }
                unsigned mk = __ballot_sync(0xFFFFFFFFu, mbit);
                int wix = c * 8 + wv;
                if (lane == 0 && wix < NWORDS) tmpm[wix] = mk;
            }
            __syncthreads();

            // warp-parallel prefix over 65 words + neighbor cutoff
            if (tid < 32) {
                unsigned mk0 = tmpm[lane];
                unsigned mk1 = tmpm[lane + 32];
                unsigned mk2 = (lane == 0) ? tmpm[64] : 0u;
                int pc0 = __popc(mk0), pc1 = __popc(mk1);
                int s = pc0;
                #pragma unroll
                for (int d = 1; d < 32; d <<= 1) { int t2 = __shfl_up_sync(0xFFFFFFFFu, s, d); if (lane >= d) s += t2; }
                int pre0 = s - pc0;
                int tot0 = __shfl_sync(0xFFFFFFFFu, s, 31);
                int s2 = pc1;
                #pragma unroll
                for (int d = 1; d < 32; d <<= 1) { int t2 = __shfl_up_sync(0xFFFFFFFFu, s2, d); if (lane >= d) s2 += t2; }
                int pre1  = tot0 + s2 - pc1;
                int tot01 = tot0 + __shfl_sync(0xFFFFFFFFu, s2, 31);

                apply_word(sup, selb, lane,      mk0, pre0);
                apply_word(sup, selb, lane + 32, mk1, pre1);
                if (lane == 0) apply_word(sup, selb, 64, mk2, tot01);
                __syncwarp();
                if (lane == 0) {
                    sup[i >> 5]  |= 1u << (i & 31);
                    selb[i >> 5] |= 1u << (i & 31);
                }
            }
            __syncthreads();
            cnt++; i++;
        }
    }
    __syncthreads();

    // ---- Warp-parallel exclusive prefix counts over 65 words ----
    if (tid < 32) {
        int u0 = __popc(~sup[lane]), u1 = __popc(~sup[lane + 32]);
        int u2 = (lane == 0) ? __popc(~sup[64]) : 0;
        int s = u0;
        #pragma unroll
        for (int d = 1; d < 32; d <<= 1) { int t2 = __shfl_up_sync(0xFFFFFFFFu, s, d); if (lane >= d) s += t2; }
        Pun[lane] = s - u0;
        int tot0 = __shfl_sync(0xFFFFFFFFu, s, 31);
        int s2 = u1;
        #pragma unroll
        for (int d = 1; d < 32; d <<= 1) { int t2 = __shfl_up_sync(0xFFFFFFFFu, s2, d); if (lane >= d) s2 += t2; }
        Pun[lane + 32] = tot0 + s2 - u1;
        int totu = tot0 + __shfl_sync(0xFFFFFFFFu, s2, 31);
        if (lane == 0) { Pun[64] = totu; s_nunsup = totu + u2; }

        int v0 = __popc(selb[lane]), v1 = __popc(selb[lane + 32]);
        int v2 = (lane == 0) ? __popc(selb[64]) : 0;
        int t3 = v0;
        #pragma unroll
        for (int d = 1; d < 32; d <<= 1) { int t2 = __shfl_up_sync(0xFFFFFFFFu, t3, d); if (lane >= d) t3 += t2; }
        Psel[lane] = t3 - v0;
        int st0 = __shfl_sync(0xFFFFFFFFu, t3, 31);
        int t4 = v1;
        #pragma unroll
        for (int d = 1; d < 32; d <<= 1) { int t2 = __shfl_up_sync(0xFFFFFFFFu, t4, d); if (lane >= d) t4 += t2; }
        Psel[lane + 32] = st0 + t4 - v1;
        int tots = st0 + __shfl_sync(0xFFFFFFFFu, t4, 31);
        if (lane == 0) { Psel[64] = tots; s_pad = TOTAL - (tots + v2); }
    }
    __syncthreads();

    // ---- Parallel emit of neg/mid position lists by rank ----
    if (tid < NWORDS) {
        const int w = tid;
        const int pad = s_pad, nun = s_nunsup;
        unsigned un = ~sup[w];
        int rank = Pun[w];
        while (un) {
            int bp = __ffs(un) - 1; un &= un - 1;
            int pos = (w << 5) + bp;
            if (rank == 0) s_first = pos;
            if (rank < pad) midpos[rank] = pos;
            int back = nun - 1 - rank;
            if (back >= 0 && back < NEGATIVE) negpos[back] = pos;
            rank++;
        }
        unsigned sl = selb[w];
        int rs = Psel[w];
        while (sl) {
            int bp = __ffs(sl) - 1; sl &= sl - 1;
            int pos = (w << 5) + bp;
            int slot = pad + rs;
            if (slot < TOTAL) midpos[slot] = pos;
            rs++;
        }
    }
    __syncthreads();
    if (tid < NEGATIVE && tid >= s_nunsup) negpos[tid] = s_first;
    __syncthreads();

    // ---- Epilogue: scalar outputs + cell indices ----
    if (tid < KOUT) {
        int pos = (tid < NEGATIVE) ? negpos[tid] : midpos[tid - NEGATIVE];
        int m = (int)(fkeys[pos] & 0xFFFFFFFFu);
        int r = rtab[m], c = ctab[m];
        int k = b * KOUT + tid;
        int cell = (b * NN + r) * NN + c;
        g_cell[k] = cell;
        out[F1 + 2 * k]     = (float)r;
        out[F1 + 2 * k + 1] = (float)(c + 1);
        out[F2 + 2 * k]     = offset_gt[(size_t)cell * 2];
        out[F2 + 2 * k + 1] = offset_gt[(size_t)cell * 2 + 1];
        out[F3 + k]         = tmap[cell];
    }
}

// Pure feature copy: 1616 blocks * 256 threads * 1 float4 = 413696 = BK*128 exactly
__global__ __launch_bounds__(256)
void feat_copy(const float* __restrict__ map2d, float* __restrict__ out)
{
    const int i = blockIdx.x * 256 + threadIdx.x;   // 0..413695
    const int k = i >> 7, t = i & 127;
    const int cell = g_cell[k];
    float4 val = ((const float4*)(map2d + (size_t)cell * DD))[t];
    ((float4*)out)[(size_t)k * 128 + t] = val;
}

extern "C" void kernel_launch(void* const* d_in, const int* in_sizes, int n_in,
                              void* d_out, int out_size)
{
    // Inputs: score_pred, map2d_mask(bool, ignored), map2d, offset_gt, tmap
    const float* score = (const float*)d_in[0];
    int o = (n_in >= 5) ? 1 : 0;
    const float* map2d  = (const float*)d_in[1 + o];
    const float* offg   = (const float*)d_in[2 + o];
    const float* tm     = (const float*)d_in[3 + o];
    float* out = (float*)d_out;

    select_kernel<<<BB, THRS>>>(score, offg, tm, out);
    feat_copy<<<3232 * 128 / 256, 256>>>(map2d, out);
}

// round 9
// speedup vs baseline: 1.6169x; 1.6169x over previous
#include <cuda_runtime.h>
#include <cuda_bf16.h>

// Problem constants
#define NN        64
#define MM        2080          // N*(N+1)/2
#define NWORDS    65            // 2080/32
#define TOPK      5
#define NEIGHBOR  16
#define NEGATIVE  16
#define TOTAL     85
#define KOUT      101
#define BB        32
#define DD        512
#define SORTM     2048
#define NEXTRA    32            // MM - SORTM
#define THRS      256           // 8 warps, 8 keys/thread

#define BK        (BB*KOUT)     // 3232
#define F1        (BK*DD)
#define F2        (F1 + BK*2)
#define F3        (F2 + BK*2)

__device__ int g_cell[BK];      // (b*NN+r)*NN+c per output row

__device__ __forceinline__ int tri_base(int r) { return r * (129 - r) / 2; }

__device__ __forceinline__ void cswap(unsigned long long& a, unsigned long long& b, bool up)
{
    if ((a > b) == up) { unsigned long long t = a; a = b; b = t; }
}

// In-register bitonic stage, J in {1,2,4}, over 8 elements with base index el0
template<int J, int K>
__device__ __forceinline__ void sreg(unsigned long long v[8], int el0)
{
    #pragma unroll
    for (int r = 0; r < 8; r++)
        if ((r & J) == 0) cswap(v[r], v[r + J], ((el0 + r) & K) == 0);
}

// Strided-register bitonic stage for the high-j exchanges:
// element at array position p = m*256 + tid; for j>=256, p&j and p&k depend
// only on m, so stage (j,k) == sreg<j/256, k/256> on the strided vector.
template<int JD, int KD>   // JD = j/256, KD = k/256
__device__ __forceinline__ void sstr(unsigned long long w[8])
{
    #pragma unroll
    for (int m = 0; m < 8; m++)
        if ((m & JD) == 0) cswap(w[m], w[m + JD], (m & KD) == 0);
}

// Shuffle bitonic stage, J in {8..128}: partner lane = lane ^ (J/8)
template<int J, int K>
__device__ __forceinline__ void sshf(unsigned long long v[8], int el0)
{
    #pragma unroll
    for (int r = 0; r < 8; r++) {
        unsigned long long o = __shfl_xor_sync(0xFFFFFFFFu, v[r], J >> 3);
        int e = el0 + r;
        bool tm = (((e & J) == 0) == ((e & K) == 0));
        v[r] = ((v[r] < o) == tm) ? v[r] : o;
    }
}

// Warp-local tail of phase K (>=512): j = 128..1, contiguous layout
template<int K>
__device__ __forceinline__ void tail8(unsigned long long v[8], int e0)
{
    sshf<128,K>(v,e0); sshf<64,K>(v,e0); sshf<32,K>(v,e0);
    sshf<16,K>(v,e0);  sshf<8,K>(v,e0);
    sreg<4,K>(v,e0);   sreg<2,K>(v,e0);  sreg<1,K>(v,e0);
}

// count of elements < key in ascending a[0..32). unique keys.
__device__ __forceinline__ int lb32(const unsigned long long* __restrict__ a,
                                    unsigned long long key)
{
    int lo = 0;
    #pragma unroll
    for (int s = 16; s >= 1; s >>= 1)
        if (a[lo + s - 1] < key) lo += s;
    return lo + ((a[lo] < key) ? 1 : 0);
}

// count of elements < key in ascending a[0..2048).
__device__ __forceinline__ int lb2048(const unsigned long long* __restrict__ a,
                                      unsigned long long key)
{
    int lo = 0;
    #pragma unroll
    for (int s = 1024; s >= 1; s >>= 1)
        if (a[lo + s - 1] < key) lo += s;
    return lo + ((a[lo] < key) ? 1 : 0);
}

__device__ __forceinline__ unsigned long long packkey(
    const float* sp, const unsigned char* rt, const unsigned char* ct, int m)
{
    unsigned u  = __float_as_uint(sp[(int)rt[m] * NN + (int)ct[m]]);
    unsigned sa = (u & 0x80000000u) ? ~u : (u | 0x80000000u);
    return ((unsigned long long)(~sa) << 32) | (unsigned)m;   // descending score, stable
}

// nbm = lowest `NEIGHBOR-cb` set bits (earliest sorted positions); OR into state
__device__ __forceinline__ void apply_word(unsigned* sup, unsigned* selb, int w, unsigned mk, int cb)
{
    sup[w] |= mk;
    unsigned nbm = 0u;
    if (cb < NEIGHBOR) {
        int keep = NEIGHBOR - cb;
        nbm = mk;
        int pc = __popc(mk);
        while (pc > keep) { nbm ^= (0x80000000u >> __clz(nbm)); pc--; }
    }
    selb[w] |= nbm;
}

__global__ __launch_bounds__(THRS)
void select_kernel(const float* __restrict__ score_pred,
                   const float* __restrict__ offset_gt,
                   const float* __restrict__ tmap,
                   float* __restrict__ out)
{
    __shared__ unsigned long long keys[SORTM];
    __shared__ unsigned long long fkeys[MM];       // merged final order
    __shared__ unsigned long long extras[NEXTRA];  // ascending
    __shared__ unsigned char rtab[MM], ctab[MM];
    __shared__ unsigned short se[MM];              // packed (s | e<<8) per sorted pos
    __shared__ unsigned int sup[NWORDS], selb[NWORDS], tmpm[NWORDS];
    __shared__ int Pun[NWORDS], Psel[NWORDS];
    __shared__ int midpos[TOTAL], negpos[NEGATIVE];
    __shared__ int s_nunsup, s_pad, s_first;

    const int b    = blockIdx.x;
    const int tid  = threadIdx.x;
    const int lane = tid & 31;
    const int wv   = tid >> 5;
    const int e0   = tid * 8;         // contiguous ownership base (global position)

    if (tid < NN) {
        int r = tid, base = tri_base(r);
        for (int c = r; c < NN; c++) {
            rtab[base + c - r] = (unsigned char)r;
            ctab[base + c - r] = (unsigned char)c;
        }
    }
    if (tid < NWORDS) { sup[tid] = 0u; selb[tid] = 0u; }
    if (tid < TOTAL)    midpos[tid] = MM - 1;
    if (tid < NEGATIVE) negpos[tid] = MM - 1;
    if (tid == 0) s_first = MM - 1;
    __syncthreads();

    const float* sp = score_pred + (size_t)b * NN * NN;
    unsigned long long v[8];
    #pragma unroll
    for (int r = 0; r < 8; r++) v[r] = packkey(sp, rtab, ctab, e0 + r);

    // ---- Phase A: k = 2..256 entirely warp-local (global-position directions) ----
    sreg<1,2>(v,e0);
    sreg<2,4>(v,e0);  sreg<1,4>(v,e0);
    sreg<4,8>(v,e0);  sreg<2,8>(v,e0);  sreg<1,8>(v,e0);
    sshf<8,16>(v,e0); sreg<4,16>(v,e0); sreg<2,16>(v,e0); sreg<1,16>(v,e0);
    sshf<16,32>(v,e0); sshf<8,32>(v,e0);
    sreg<4,32>(v,e0);  sreg<2,32>(v,e0); sreg<1,32>(v,e0);
    sshf<32,64>(v,e0); sshf<16,64>(v,e0); sshf<8,64>(v,e0);
    sreg<4,64>(v,e0);  sreg<2,64>(v,e0);  sreg<1,64>(v,e0);
    sshf<64,128>(v,e0); sshf<32,128>(v,e0); sshf<16,128>(v,e0); sshf<8,128>(v,e0);
    sreg<4,128>(v,e0);  sreg<2,128>(v,e0);  sreg<1,128>(v,e0);
    sshf<128,256>(v,e0); sshf<64,256>(v,e0); sshf<32,256>(v,e0);
    sshf<16,256>(v,e0);  sshf<8,256>(v,e0);
    sreg<4,256>(v,e0);   sreg<2,256>(v,e0); sreg<1,256>(v,e0);

    #pragma unroll
    for (int r = 0; r < 8; r++) keys[e0 + r] = v[r];

    // ---- Warp 0 sorts the 32 extras (ascending, shuffle bitonic) ----
    unsigned long long ek = 0;
    if (wv == 0) {
        ek = packkey(sp, rtab, ctab, SORTM + lane);
        #pragma unroll
        for (int kk = 2; kk <= 32; kk <<= 1)
            #pragma unroll
            for (int j = kk >> 1; j >= 1; j >>= 1) {
                unsigned long long o = __shfl_xor_sync(0xFFFFFFFFu, ek, j);
                bool tm = (((lane & j) == 0) == ((lane & kk) == 0));
                ek = ((ek < o) == tm) ? ek : o;
            }
        extras[lane] = ek;
    }
    __syncthreads();

    unsigned long long w[8];

    // ---- Phase k=512: strided pass does j=256; tail does j<=128 ----
    #pragma unroll
    for (int m = 0; m < 8; m++) w[m] = keys[m * 256 + tid];
    sstr<1,2>(w);                                   // j=256, k=512
    #pragma unroll
    for (int m = 0; m < 8; m++) keys[m * 256 + tid] = w[m];
    __syncthreads();
    #pragma unroll
    for (int r = 0; r < 8; r++) v[r] = keys[e0 + r];
    tail8<512>(v, e0);
    #pragma unroll
    for (int r = 0; r < 8; r++) keys[e0 + r] = v[r];
    __syncthreads();

    // ---- Phase k=1024: strided pass does j=512,256 ----
    #pragma unroll
    for (int m = 0; m < 8; m++) w[m] = keys[m * 256 + tid];
    sstr<2,4>(w); sstr<1,4>(w);                     // j=512,256, k=1024
    #pragma unroll
    for (int m = 0; m < 8; m++) keys[m * 256 + tid] = w[m];
    __syncthreads();
    #pragma unroll
    for (int r = 0; r < 8; r++) v[r] = keys[e0 + r];
    tail8<1024>(v, e0);
    #pragma unroll
    for (int r = 0; r < 8; r++) keys[e0 + r] = v[r];
    __syncthreads();

    // ---- Phase k=2048: strided pass does j=1024,512,256 ----
    #pragma unroll
    for (int m = 0; m < 8; m++) w[m] = keys[m * 256 + tid];
    sstr<4,8>(w); sstr<2,8>(w); sstr<1,8>(w);       // j=1024,512,256, k=2048
    #pragma unroll
    for (int m = 0; m < 8; m++) keys[m * 256 + tid] = w[m];
    __syncthreads();
    #pragma unroll
    for (int r = 0; r < 8; r++) v[r] = keys[e0 + r];
    tail8<2048>(v, e0);                             // v = fully sorted, positions e0..e0+7
    #pragma unroll
    for (int r = 0; r < 8; r++) keys[e0 + r] = v[r];
    __syncthreads();

    // ---- Merge scatter of extras (keys unique -> ranks form a permutation) ----
    #pragma unroll
    for (int r = 0; r < 8; r++) {
        unsigned long long x = v[r];
        int rank = e0 + r + lb32(extras, x);        // shift by #extras below
        int m = (int)(x & 0xFFFFFFFFu);
        fkeys[rank] = x;
        se[rank] = (unsigned short)((int)rtab[m] | (((int)ctab[m] + 1) << 8));
    }
    if (wv == 0) {
        int rank = lb2048(keys, ek) + lane;         // mains below + own rank among extras
        int m = (int)(ek & 0xFFFFFFFFu);
        fkeys[rank] = ek;
        se[rank] = (unsigned short)((int)rtab[m] | (((int)ctab[m] + 1) << 8));
    }
    __syncthreads();

    // ---- Cache this thread's 9 se values in registers ----
    unsigned short se9[9];
    #pragma unroll
    for (int c = 0; c < 9; c++) {
        int pos = c * THRS + tid;
        se9[c] = (pos < MM) ? se[pos] : (unsigned short)0;
    }

    // ---- Greedy selection: <= TOPK heavy iterations ----
    {
        int i = 0, cnt = 0;
        while (cnt < TOPK && i < MM - 1) {
            if ((sup[i >> 5] >> (i & 31)) & 1u) { i++; continue; }
            int se0 = se[i];
            int s0 = se0 & 0xFF, eH = se0 >> 8;

            #pragma unroll
            for (int c = 0; c < 9; c++) {
                int pos = c * THRS + tid;
                bool mbit = false;
                if (pos < MM && pos > i) {
                    int se1 = se9[c];
                    int s1 = se1 & 0xFF, e1 = se1 >> 8;
                    int inter = min(e1, eH) - max(s1, s0);
                    int uni   = max(e1, eH) - min(s1, s0);
                    mbit = (inter > 0) && (2 * inter > uni);   // iou > 0.5 exact
                }
                unsigned mk = __ballot_sync(0xFFFFFFFFu, mbit);
                int wix = c * 8 + wv;
                if (lane == 0 && wix < NWORDS) tmpm[wix] = mk;
            }
            __syncthreads();

            // warp-parallel prefix over 65 words + neighbor cutoff
            if (tid < 32) {
                unsigned mk0 = tmpm[lane];
                unsigned mk1 = tmpm[lane + 32];
                unsigned mk2 = (lane == 0) ? tmpm[64] : 0u;
                int pc0 = __popc(mk0), pc1 = __popc(mk1);
                int s = pc0;
                #pragma unroll
                for (int d = 1; d < 32; d <<= 1) { int t2 = __shfl_up_sync(0xFFFFFFFFu, s, d); if (lane >= d) s += t2; }
                int pre0 = s - pc0;
                int tot0 = __shfl_sync(0xFFFFFFFFu, s, 31);
                int s2 = pc1;
                #pragma unroll
                for (int d = 1; d < 32; d <<= 1) { int t2 = __shfl_up_sync(0xFFFFFFFFu, s2, d); if (lane >= d) s2 += t2; }
                int pre1  = tot0 + s2 - pc1;
                int tot01 = tot0 + __shfl_sync(0xFFFFFFFFu, s2, 31);

                apply_word(sup, selb, lane,      mk0, pre0);
                apply_word(sup, selb, lane + 32, mk1, pre1);
                if (lane == 0) apply_word(sup, selb, 64, mk2, tot01);
                __syncwarp();
                if (lane == 0) {
                    sup[i >> 5]  |= 1u << (i & 31);
                    selb[i >> 5] |= 1u << (i & 31);
                }
            }
            __syncthreads();
            cnt++; i++;
        }
    }
    __syncthreads();

    // ---- Warp-parallel exclusive prefix counts over 65 words ----
    if (tid < 32) {
        int u0 = __popc(~sup[lane]), u1 = __popc(~sup[lane + 32]);
        int u2 = (lane == 0) ? __popc(~sup[64]) : 0;
        int s = u0;
        #pragma unroll
        for (int d = 1; d < 32; d <<= 1) { int t2 = __shfl_up_sync(0xFFFFFFFFu, s, d); if (lane >= d) s += t2; }
        Pun[lane] = s - u0;
        int tot0 = __shfl_sync(0xFFFFFFFFu, s, 31);
        int s2 = u1;
        #pragma unroll
        for (int d = 1; d < 32; d <<= 1) { int t2 = __shfl_up_sync(0xFFFFFFFFu, s2, d); if (lane >= d) s2 += t2; }
        Pun[lane + 32] = tot0 + s2 - u1;
        int totu = tot0 + __shfl_sync(0xFFFFFFFFu, s2, 31);
        if (lane == 0) { Pun[64] = totu; s_nunsup = totu + u2; }

        int v0 = __popc(selb[lane]), v1 = __popc(selb[lane + 32]);
        int v2 = (lane == 0) ? __popc(selb[64]) : 0;
        int t3 = v0;
        #pragma unroll
        for (int d = 1; d < 32; d <<= 1) { int t2 = __shfl_up_sync(0xFFFFFFFFu, t3, d); if (lane >= d) t3 += t2; }
        Psel[lane] = t3 - v0;
        int st0 = __shfl_sync(0xFFFFFFFFu, t3, 31);
        int t4 = v1;
        #pragma unroll
        for (int d = 1; d < 32; d <<= 1) { int t2 = __shfl_up_sync(0xFFFFFFFFu, t4, d); if (lane >= d) t4 += t2; }
        Psel[lane + 32] = st0 + t4 - v1;
        int tots = st0 + __shfl_sync(0xFFFFFFFFu, t4, 31);
        if (lane == 0) { Psel[64] = tots; s_pad = TOTAL - (tots + v2); }
    }
    __syncthreads();

    // ---- Parallel emit of neg/mid position lists by rank ----
    if (tid < NWORDS) {
        const int wq = tid;
        const int pad = s_pad, nun = s_nunsup;
        unsigned un = ~sup[wq];
        int rank = Pun[wq];
        while (un) {
            int bp = __ffs(un) - 1; un &= un - 1;
            int pos = (wq << 5) + bp;
            if (rank == 0) s_first = pos;
            if (rank < pad) midpos[rank] = pos;
            int back = nun - 1 - rank;
            if (back >= 0 && back < NEGATIVE) negpos[back] = pos;
            rank++;
        }
        unsigned sl = selb[wq];
        int rs = Psel[wq];
        while (sl) {
            int bp = __ffs(sl) - 1; sl &= sl - 1;
            int pos = (wq << 5) + bp;
            int slot = pad + rs;
            if (slot < TOTAL) midpos[slot] = pos;
            rs++;
        }
    }
    __syncthreads();
    if (tid < NEGATIVE && tid >= s_nunsup) negpos[tid] = s_first;
    __syncthreads();

    // ---- Epilogue: scalar outputs + cell indices ----
    if (tid < KOUT) {
        int pos = (tid < NEGATIVE) ? negpos[tid] : midpos[tid - NEGATIVE];
        int m = (int)(fkeys[pos] & 0xFFFFFFFFu);
        int r = rtab[m], c = ctab[m];
        int k = b * KOUT + tid;
        int cell = (b * NN + r) * NN + c;
        g_cell[k] = cell;
        out[F1 + 2 * k]     = (float)r;
        out[F1 + 2 * k + 1] = (float)(c + 1);
        out[F2 + 2 * k]     = offset_gt[(size_t)cell * 2];
        out[F2 + 2 * k + 1] = offset_gt[(size_t)cell * 2 + 1];
        out[F3 + k]         = tmap[cell];
    }
}

// Pure feature copy: 1616 blocks * 256 threads * 1 float4 = 413696 = BK*128 exactly
__global__ __launch_bounds__(256)
void feat_copy(const float* __restrict__ map2d, float* __restrict__ out)
{
    const int i = blockIdx.x * 256 + threadIdx.x;   // 0..413695
    const int k = i >> 7, t = i & 127;
    const int cell = g_cell[k];
    float4 val = ((const float4*)(map2d + (size_t)cell * DD))[t];
    ((float4*)out)[(size_t)k * 128 + t] = val;
}

extern "C" void kernel_launch(void* const* d_in, const int* in_sizes, int n_in,
                              void* d_out, int out_size)
{
    // Inputs: score_pred, map2d_mask(bool, ignored), map2d, offset_gt, tmap
    const float* score = (const float*)d_in[0];
    int o = (n_in >= 5) ? 1 : 0;
    const float* map2d  = (const float*)d_in[1 + o];
    const float* offg   = (const float*)d_in[2 + o];
    const float* tm     = (const float*)d_in[3 + o];
    float* out = (float*)d_out;

    select_kernel<<<BB, THRS>>>(score, offg, tm, out);
    feat_copy<<<3232 * 128 / 256, 256>>>(map2d, out);
}